// round 2
// baseline (speedup 1.0000x reference)
#include <cuda_runtime.h>

#define Bq 32
#define Tq 512
#define Dq 128
#define Nq 1024
#define NOISE_C 0.001f
#define GRID_G 128
#define NCOL 8

// States double buffer, k-blocked transposed: g_S4[phase][k/4][b] = float4 of S[b][4k..4k+3]
__device__ float4 g_S4[2][Nq / 4][Bq];
// Distributed grid-barrier flags (monotonic generations; zero-init; never reset -> replay-safe)
__device__ unsigned g_arr[GRID_G];

__device__ __forceinline__ void grid_bar(unsigned target) {
    __syncthreads();
    if (threadIdx.x == 0) {
        __threadfence();  // release: make g_S writes visible in L2 before flagging
        *(volatile unsigned*)&g_arr[blockIdx.x] = target;
    }
    if (threadIdx.x < GRID_G) {
        while (*(volatile unsigned*)&g_arr[threadIdx.x] < target) __nanosleep(32);
    }
    __syncthreads();
}

// out[:,0,:] = step0 ; pack states0 into g_S4[0]
__global__ void init_kernel(const float* __restrict__ states0,
                            const float* __restrict__ step0,
                            float* __restrict__ out) {
    int i = blockIdx.x * blockDim.x + threadIdx.x;  // 0 .. 32767
    int b = i >> 10;
    int n = i & 1023;
    out[(size_t)b * Tq * Nq + n] = step0[i];
    ((float*)&g_S4[0][n >> 2][b])[n & 3] = states0[i];
}

// xin GEMM: out[b,t,n] = scale * sum_d x[b,t,d] * w_input[d,n]   for t in [1,512)
// M = 32*511 = 16352 rows, K = 128, N = 1024. Block tile 128x128, thread tile 8x8.
__global__ __launch_bounds__(256) void xin_gemm(const float* __restrict__ x,
                                                const float* __restrict__ w_in,
                                                const float* __restrict__ scale_p,
                                                float* __restrict__ out) {
    __shared__ float xs[128][33];
    __shared__ float ws[32][132];
    __shared__ int rowoff[128];

    const int tid = threadIdx.x;
    const int tx = tid & 15;
    const int ty = tid >> 4;
    const int bn = blockIdx.x;   // 0..7
    const int bm = blockIdx.y;   // 0..127
    const float sc = *scale_p;

    if (tid < 128) {
        int m = bm * 128 + tid;
        if (m < Bq * (Tq - 1)) {
            int b = m / (Tq - 1);
            int t = m - b * (Tq - 1) + 1;
            rowoff[tid] = (b * Tq + t) * Dq;   // byte-free float offset into x
        } else {
            rowoff[tid] = -1;
        }
    }

    float acc[8][8];
#pragma unroll
    for (int i = 0; i < 8; ++i)
#pragma unroll
        for (int j = 0; j < 8; ++j) acc[i][j] = 0.f;

    __syncthreads();

    for (int kc = 0; kc < 4; ++kc) {
#pragma unroll
        for (int l = 0; l < 16; ++l) {           // 128x32 x-tile
            int idx = tid + l * 256;
            int r = idx >> 5, k = idx & 31;
            int ro = rowoff[r];
            xs[r][k] = (ro >= 0) ? x[(size_t)ro + kc * 32 + k] : 0.f;
        }
#pragma unroll
        for (int l = 0; l < 16; ++l) {           // 32x128 w-tile
            int idx = tid + l * 256;
            int kk = idx >> 7, c = idx & 127;
            ws[kk][c] = w_in[(size_t)(kc * 32 + kk) * Nq + bn * 128 + c];
        }
        __syncthreads();

#pragma unroll
        for (int k = 0; k < 32; ++k) {
            float xr[8], wr[8];
#pragma unroll
            for (int i = 0; i < 8; ++i) xr[i] = xs[ty * 8 + i][k];
#pragma unroll
            for (int j = 0; j < 8; ++j) wr[j] = ws[k][tx * 8 + j];
#pragma unroll
            for (int i = 0; i < 8; ++i)
#pragma unroll
                for (int j = 0; j < 8; ++j) acc[i][j] += xr[i] * wr[j];
        }
        __syncthreads();
    }

#pragma unroll
    for (int i = 0; i < 8; ++i) {
        int ro = rowoff[ty * 8 + i];
        if (ro < 0) continue;
        float* op = out + (size_t)(ro >> 7) * Nq + bn * 128 + tx * 8;  // ro/Dq * Nq
#pragma unroll
        for (int j = 0; j < 8; ++j) op[j] = acc[i][j] * sc;
    }
}

// Persistent recurrence kernel. 128 CTAs x 256 threads. CTA owns 8 columns of W_res
// (SMEM-resident). Warp w reduces K-slice [128w,128w+128), lane = batch index.
// Packed fp32x2 FMA (FFMA2) doubles fp32 throughput vs 3-reg FFMA (rt 2 -> eff 1).
__global__ __launch_bounds__(256) void recur_kernel(const float* __restrict__ w_res,
                                                    const float* __restrict__ noise,
                                                    float* __restrict__ out) {
    __shared__ __align__(16) float Wsm[Nq][NCOL];  // 32 KB
    __shared__ float red[8][Bq][9];                // padded, conflict-free
    __shared__ unsigned s_start;

    const int tid = threadIdx.x;
    const int cta = blockIdx.x;
    const int col0 = cta * NCOL;

    for (int i = tid; i < Nq * NCOL; i += 256) {
        int k = i >> 3, c = i & 7;
        Wsm[k][c] = w_res[(size_t)k * Nq + col0 + c];
    }
    if (tid == 0) s_start = *(volatile unsigned*)&g_arr[cta];  // monotonic base (replay-safe)
    __syncthreads();
    const unsigned sg = s_start;

    const int warp = tid >> 5;
    const int lane = tid & 31;  // = batch b for the K-reduction

    // epilogue mapping: thread -> (eb, ec)
    const int eb = tid >> 3;
    const int ec = tid & 7;
    const int en = col0 + ec;
    const float nz = NOISE_C * noise[eb * Nq + en];
    float* outp = out + (size_t)eb * Tq * Nq + en;
    float* sW0 = &((float*)&g_S4[0][en >> 2][eb])[en & 3];
    float* sW1 = &((float*)&g_S4[1][en >> 2][eb])[en & 3];

    const ulonglong2* Wp0 = (const ulonglong2*)&Wsm[warp * 128][0];

    for (int t = 1; t < Tq; ++t) {
        const float4* Sp = ((const float4*)g_S4[(t - 1) & 1]) + warp * (32 * Bq) + lane;

        unsigned long long a0 = 0, a1 = 0, a2 = 0, a3 = 0;
        const ulonglong2* wp = Wp0;

#pragma unroll 4
        for (int it = 0; it < 32; ++it) {
            float4 s = __ldcg(Sp);  // L2-only: written by peer SMs, L1 would be stale
            Sp += Bq;
#pragma unroll
            for (int kk = 0; kk < 4; ++kk) {
                unsigned sb = __float_as_uint(kk == 0 ? s.x : kk == 1 ? s.y
                                                         : kk == 2 ? s.z : s.w);
                unsigned long long svv;
                asm("mov.b64 %0, {%1, %1};" : "=l"(svv) : "r"(sb));
                ulonglong2 u0 = wp[0];
                ulonglong2 u1 = wp[1];
                wp += 2;
                asm("fma.rn.f32x2 %0, %1, %2, %0;" : "+l"(a0) : "l"(svv), "l"(u0.x));
                asm("fma.rn.f32x2 %0, %1, %2, %0;" : "+l"(a1) : "l"(svv), "l"(u0.y));
                asm("fma.rn.f32x2 %0, %1, %2, %0;" : "+l"(a2) : "l"(svv), "l"(u1.x));
                asm("fma.rn.f32x2 %0, %1, %2, %0;" : "+l"(a3) : "l"(svv), "l"(u1.y));
            }
        }

        red[warp][lane][0] = __uint_as_float((unsigned)a0);
        red[warp][lane][1] = __uint_as_float((unsigned)(a0 >> 32));
        red[warp][lane][2] = __uint_as_float((unsigned)a1);
        red[warp][lane][3] = __uint_as_float((unsigned)(a1 >> 32));
        red[warp][lane][4] = __uint_as_float((unsigned)a2);
        red[warp][lane][5] = __uint_as_float((unsigned)(a2 >> 32));
        red[warp][lane][6] = __uint_as_float((unsigned)a3);
        red[warp][lane][7] = __uint_as_float((unsigned)(a3 >> 32));
        __syncthreads();

        float sum = 0.f;
#pragma unroll
        for (int w = 0; w < 8; ++w) sum += red[w][eb][ec];

        float xin = outp[(size_t)t * Nq];        // our own 32B sector only — L1-safe
        float post = tanhf(sum + xin) + nz;
        outp[(size_t)t * Nq] = post;
        *((t & 1) ? sW1 : sW0) = post;

        grid_bar(sg + (unsigned)t);
    }
}

extern "C" void kernel_launch(void* const* d_in, const int* in_sizes, int n_in,
                              void* d_out, int out_size) {
    (void)in_sizes; (void)n_in; (void)out_size;
    const float* x       = (const float*)d_in[0];
    const float* w_input = (const float*)d_in[1];
    const float* w_res   = (const float*)d_in[2];
    const float* w_scale = (const float*)d_in[3];
    const float* states0 = (const float*)d_in[4];
    const float* step0   = (const float*)d_in[5];
    const float* rnoise  = (const float*)d_in[6];
    float* out = (float*)d_out;

    init_kernel<<<128, 256>>>(states0, step0, out);
    dim3 g(8, 128);
    xin_gemm<<<g, 256>>>(x, w_input, w_scale, out);
    recur_kernel<<<GRID_G, 256>>>(w_res, rnoise, out);
}

// round 3
// speedup vs baseline: 2.1699x; 2.1699x over previous
#include <cuda_runtime.h>

#define Bq 32
#define Tq 512
#define Dq 128
#define Nq 1024
#define NOISE_C 0.001f
#define GRID_G 128
#define NCOL 8

// States double buffer, k-blocked transposed: g_S4[phase][k/4][b] = float4 of S[b][4k..4k+3]
__device__ float4 g_S4[2][Nq / 4][Bq];
// Monotonic arrival counter for the grid barrier. Reset by init_kernel each launch
// (stream-ordered before recur_kernel) -> deterministic & graph-replay-safe.
__device__ unsigned g_count;

// out[:,0,:] = step0 ; pack states0 into g_S4[0] ; reset barrier counter
__global__ void init_kernel(const float* __restrict__ states0,
                            const float* __restrict__ step0,
                            float* __restrict__ out) {
    int i = blockIdx.x * blockDim.x + threadIdx.x;  // 0 .. 32767
    int b = i >> 10;
    int n = i & 1023;
    out[(size_t)b * Tq * Nq + n] = step0[i];
    ((float*)&g_S4[0][n >> 2][b])[n & 3] = states0[i];
    if (i == 0) g_count = 0u;
}

// xin GEMM: out[b,t,n] = scale * sum_d x[b,t,d] * w_input[d,n]   for t in [1,512)
// M = 32*511 = 16352 rows, K = 128, N = 1024. Block tile 128x128, thread tile 8x8.
__global__ __launch_bounds__(256) void xin_gemm(const float* __restrict__ x,
                                                const float* __restrict__ w_in,
                                                const float* __restrict__ scale_p,
                                                float* __restrict__ out) {
    __shared__ float xs[128][33];
    __shared__ float ws[32][132];
    __shared__ int rowoff[128];

    const int tid = threadIdx.x;
    const int tx = tid & 15;
    const int ty = tid >> 4;
    const int bn = blockIdx.x;   // 0..7
    const int bm = blockIdx.y;   // 0..127
    const float sc = *scale_p;

    if (tid < 128) {
        int m = bm * 128 + tid;
        if (m < Bq * (Tq - 1)) {
            int b = m / (Tq - 1);
            int t = m - b * (Tq - 1) + 1;
            rowoff[tid] = (b * Tq + t) * Dq;
        } else {
            rowoff[tid] = -1;
        }
    }

    float acc[8][8];
#pragma unroll
    for (int i = 0; i < 8; ++i)
#pragma unroll
        for (int j = 0; j < 8; ++j) acc[i][j] = 0.f;

    __syncthreads();

    for (int kc = 0; kc < 4; ++kc) {
#pragma unroll
        for (int l = 0; l < 16; ++l) {           // 128x32 x-tile
            int idx = tid + l * 256;
            int r = idx >> 5, k = idx & 31;
            int ro = rowoff[r];
            xs[r][k] = (ro >= 0) ? x[(size_t)ro + kc * 32 + k] : 0.f;
        }
#pragma unroll
        for (int l = 0; l < 16; ++l) {           // 32x128 w-tile
            int idx = tid + l * 256;
            int kk = idx >> 7, c = idx & 127;
            ws[kk][c] = w_in[(size_t)(kc * 32 + kk) * Nq + bn * 128 + c];
        }
        __syncthreads();

#pragma unroll
        for (int k = 0; k < 32; ++k) {
            float xr[8], wr[8];
#pragma unroll
            for (int i = 0; i < 8; ++i) xr[i] = xs[ty * 8 + i][k];
#pragma unroll
            for (int j = 0; j < 8; ++j) wr[j] = ws[k][tx * 8 + j];
#pragma unroll
            for (int i = 0; i < 8; ++i)
#pragma unroll
                for (int j = 0; j < 8; ++j) acc[i][j] += xr[i] * wr[j];
        }
        __syncthreads();
    }

#pragma unroll
    for (int i = 0; i < 8; ++i) {
        int ro = rowoff[ty * 8 + i];
        if (ro < 0) continue;
        float* op = out + (size_t)(ro >> 7) * Nq + bn * 128 + tx * 8;
#pragma unroll
        for (int j = 0; j < 8; ++j) op[j] = acc[i][j] * sc;
    }
}

// Persistent recurrence kernel. 128 CTAs x 256 threads. CTA owns 8 columns of W_res
// (SMEM-resident). Warp w reduces K-slice [128w,128w+128), lane = batch index.
// fp32x2 packed FMA (FFMA2) for 2x fp32 throughput; depth-8 software pipeline on
// the L2 state broadcast; counter-based grid barrier (1 poller/CTA, release/acquire).
__global__ __launch_bounds__(256, 1) void recur_kernel(const float* __restrict__ w_res,
                                                       const float* __restrict__ noise,
                                                       float* __restrict__ out) {
    __shared__ __align__(16) float Wsm[Nq][NCOL];  // 32 KB
    __shared__ float red[8][Bq][9];                // padded, conflict-free reads

    const int tid = threadIdx.x;
    const int cta = blockIdx.x;
    const int col0 = cta * NCOL;

    for (int i = tid; i < Nq * NCOL; i += 256) {
        int k = i >> 3, c = i & 7;
        Wsm[k][c] = w_res[(size_t)k * Nq + col0 + c];
    }
    __syncthreads();

    const int warp = tid >> 5;
    const int lane = tid & 31;  // = batch b for the K-reduction

    // epilogue mapping: thread -> (eb, ec)
    const int eb = tid >> 3;
    const int ec = tid & 7;
    const int en = col0 + ec;
    const float nz = NOISE_C * noise[eb * Nq + en];
    float* outp = out + (size_t)eb * Tq * Nq + en;
    float* sW0 = &((float*)&g_S4[0][en >> 2][eb])[en & 3];
    float* sW1 = &((float*)&g_S4[1][en >> 2][eb])[en & 3];

    const ulonglong2* Wp0 = (const ulonglong2*)&Wsm[warp * 128][0];
    unsigned* cnt = &g_count;

    for (int t = 1; t < Tq; ++t) {
        const float4* Sp = ((const float4*)g_S4[(t - 1) & 1]) + warp * (32 * Bq) + lane;

        float xin = outp[(size_t)t * Nq];  // independent of barrier; issue early

        // prologue: fill depth-8 pipeline of L2-only state loads
        float4 buf[8];
#pragma unroll
        for (int j = 0; j < 8; ++j) buf[j] = __ldcg(Sp + j * Bq);

        unsigned long long a0 = 0, a1 = 0, a2 = 0, a3 = 0;
        const ulonglong2* wp = Wp0;

#pragma unroll
        for (int it = 0; it < 32; ++it) {
            float4 s = buf[it & 7];
            if (it < 24) buf[it & 7] = __ldcg(Sp + (it + 8) * Bq);  // keep MLP=8
#pragma unroll
            for (int kk = 0; kk < 4; ++kk) {
                unsigned sb = __float_as_uint(kk == 0 ? s.x : kk == 1 ? s.y
                                                         : kk == 2 ? s.z : s.w);
                unsigned long long svv;
                asm("mov.b64 %0, {%1, %1};" : "=l"(svv) : "r"(sb));
                ulonglong2 u0 = wp[0];
                ulonglong2 u1 = wp[1];
                wp += 2;
                asm("fma.rn.f32x2 %0, %1, %2, %0;" : "+l"(a0) : "l"(svv), "l"(u0.x));
                asm("fma.rn.f32x2 %0, %1, %2, %0;" : "+l"(a1) : "l"(svv), "l"(u0.y));
                asm("fma.rn.f32x2 %0, %1, %2, %0;" : "+l"(a2) : "l"(svv), "l"(u1.x));
                asm("fma.rn.f32x2 %0, %1, %2, %0;" : "+l"(a3) : "l"(svv), "l"(u1.y));
            }
        }

        red[warp][lane][0] = __uint_as_float((unsigned)a0);
        red[warp][lane][1] = __uint_as_float((unsigned)(a0 >> 32));
        red[warp][lane][2] = __uint_as_float((unsigned)a1);
        red[warp][lane][3] = __uint_as_float((unsigned)(a1 >> 32));
        red[warp][lane][4] = __uint_as_float((unsigned)a2);
        red[warp][lane][5] = __uint_as_float((unsigned)(a2 >> 32));
        red[warp][lane][6] = __uint_as_float((unsigned)a3);
        red[warp][lane][7] = __uint_as_float((unsigned)(a3 >> 32));
        __syncthreads();

        float sum = 0.f;
#pragma unroll
        for (int w = 0; w < 8; ++w) sum += red[w][eb][ec];

        float post = tanhf(sum + xin) + nz;
        outp[(size_t)t * Nq] = post;           // only our own sector — safe
        *((t & 1) ? sW1 : sW0) = post;         // next-step state (read via __ldcg)

        // ---- grid barrier: counter arrive (release) + single acquiring poller ----
        __syncthreads();  // all CTA state writes done; establishes HB to thread 0
        if (tid == 0) {
            asm volatile("red.release.gpu.add.u32 [%0], %1;"
                         :: "l"(cnt), "r"(1u) : "memory");
            const unsigned target = (unsigned)GRID_G * (unsigned)t;
            unsigned v;
            do {
                asm volatile("ld.acquire.gpu.u32 %0, [%1];"
                             : "=r"(v) : "l"(cnt) : "memory");
                if (v < target) __nanosleep(16);
            } while (v < target);
        }
        __syncthreads();  // broadcast barrier completion to all warps
    }
}

extern "C" void kernel_launch(void* const* d_in, const int* in_sizes, int n_in,
                              void* d_out, int out_size) {
    (void)in_sizes; (void)n_in; (void)out_size;
    const float* x       = (const float*)d_in[0];
    const float* w_input = (const float*)d_in[1];
    const float* w_res   = (const float*)d_in[2];
    const float* w_scale = (const float*)d_in[3];
    const float* states0 = (const float*)d_in[4];
    const float* step0   = (const float*)d_in[5];
    const float* rnoise  = (const float*)d_in[6];
    float* out = (float*)d_out;

    init_kernel<<<128, 256>>>(states0, step0, out);
    dim3 g(8, 128);
    xin_gemm<<<g, 256>>>(x, w_input, w_scale, out);
    recur_kernel<<<GRID_G, 256>>>(w_res, rnoise, out);
}

// round 4
// speedup vs baseline: 2.2178x; 1.0220x over previous
#include <cuda_runtime.h>

#define Bq 32
#define Tq 512
#define Dq 128
#define Nq 1024
#define NOISE_C 0.001f
#define GRID_G 128
#define NCOL 8
#define NTHR 512
#define NW 16          // warps per CTA
#define KSL 64         // K-slice per warp
#define ITS 16         // KSL/4 float4 iterations

// States double buffer, k-blocked transposed: g_S4[phase][k/4][b] = float4 of S[b][4k..4k+3]
__device__ float4 g_S4[2][Nq / 4][Bq];
// Monotonic arrival counter for the grid barrier. Reset by init_kernel each launch
// (stream-ordered before recur_kernel) -> deterministic & graph-replay-safe.
__device__ unsigned g_count;

// out[:,0,:] = step0 ; pack states0 into g_S4[0] ; reset barrier counter
__global__ void init_kernel(const float* __restrict__ states0,
                            const float* __restrict__ step0,
                            float* __restrict__ out) {
    int i = blockIdx.x * blockDim.x + threadIdx.x;  // 0 .. 32767
    int b = i >> 10;
    int n = i & 1023;
    out[(size_t)b * Tq * Nq + n] = step0[i];
    ((float*)&g_S4[0][n >> 2][b])[n & 3] = states0[i];
    if (i == 0) g_count = 0u;
}

// xin GEMM: out[b,t,n] = scale * sum_d x[b,t,d] * w_input[d,n]   for t in [1,512)
__global__ __launch_bounds__(256) void xin_gemm(const float* __restrict__ x,
                                                const float* __restrict__ w_in,
                                                const float* __restrict__ scale_p,
                                                float* __restrict__ out) {
    __shared__ float xs[128][33];
    __shared__ float ws[32][132];
    __shared__ int rowoff[128];

    const int tid = threadIdx.x;
    const int tx = tid & 15;
    const int ty = tid >> 4;
    const int bn = blockIdx.x;   // 0..7
    const int bm = blockIdx.y;   // 0..127
    const float sc = *scale_p;

    if (tid < 128) {
        int m = bm * 128 + tid;
        if (m < Bq * (Tq - 1)) {
            int b = m / (Tq - 1);
            int t = m - b * (Tq - 1) + 1;
            rowoff[tid] = (b * Tq + t) * Dq;
        } else {
            rowoff[tid] = -1;
        }
    }

    float acc[8][8];
#pragma unroll
    for (int i = 0; i < 8; ++i)
#pragma unroll
        for (int j = 0; j < 8; ++j) acc[i][j] = 0.f;

    __syncthreads();

    for (int kc = 0; kc < 4; ++kc) {
#pragma unroll
        for (int l = 0; l < 16; ++l) {
            int idx = tid + l * 256;
            int r = idx >> 5, k = idx & 31;
            int ro = rowoff[r];
            xs[r][k] = (ro >= 0) ? x[(size_t)ro + kc * 32 + k] : 0.f;
        }
#pragma unroll
        for (int l = 0; l < 16; ++l) {
            int idx = tid + l * 256;
            int kk = idx >> 7, c = idx & 127;
            ws[kk][c] = w_in[(size_t)(kc * 32 + kk) * Nq + bn * 128 + c];
        }
        __syncthreads();

#pragma unroll
        for (int k = 0; k < 32; ++k) {
            float xr[8], wr[8];
#pragma unroll
            for (int i = 0; i < 8; ++i) xr[i] = xs[ty * 8 + i][k];
#pragma unroll
            for (int j = 0; j < 8; ++j) wr[j] = ws[k][tx * 8 + j];
#pragma unroll
            for (int i = 0; i < 8; ++i)
#pragma unroll
                for (int j = 0; j < 8; ++j) acc[i][j] += xr[i] * wr[j];
        }
        __syncthreads();
    }

#pragma unroll
    for (int i = 0; i < 8; ++i) {
        int ro = rowoff[ty * 8 + i];
        if (ro < 0) continue;
        float* op = out + (size_t)(ro >> 7) * Nq + bn * 128 + tx * 8;
#pragma unroll
        for (int j = 0; j < 8; ++j) op[j] = acc[i][j] * sc;
    }
}

// Persistent recurrence. 128 CTAs x 512 threads (4 warps/SMSP for latency hiding).
// CTA owns 8 columns of W_res in SMEM. Warp w reduces K-slice [64w, 64w+64),
// lane = batch. fp32x2 packed FMA; depth-8 pipelined L2-only state loads;
// counter grid barrier (1 REDG arrive + 1 acquiring poller per CTA).
__global__ __launch_bounds__(NTHR, 1) void recur_kernel(const float* __restrict__ w_res,
                                                        const float* __restrict__ noise,
                                                        float* __restrict__ out) {
    __shared__ __align__(16) float Wsm[Nq][NCOL];   // 32 KB
    __shared__ float red[NW][Bq][9];                // 18 KB, conflict-free writes

    const int tid = threadIdx.x;
    const int cta = blockIdx.x;
    const int col0 = cta * NCOL;

    for (int i = tid; i < Nq * NCOL; i += NTHR) {
        int k = i >> 3, c = i & 7;
        Wsm[k][c] = w_res[(size_t)k * Nq + col0 + c];
    }
    __syncthreads();

    const int warp = tid >> 5;
    const int lane = tid & 31;  // = batch b for the K-reduction

    // epilogue mapping (first 256 threads only): thread -> (eb, ec)
    const bool epi = (tid < Bq * NCOL);
    const int eb = (tid >> 3) & 31;
    const int ec = tid & 7;
    const int en = col0 + ec;
    const float nz = epi ? NOISE_C * noise[eb * Nq + en] : 0.f;
    float* outp = out + (size_t)eb * Tq * Nq + en;
    float* sW0 = &((float*)&g_S4[0][en >> 2][eb])[en & 3];
    float* sW1 = &((float*)&g_S4[1][en >> 2][eb])[en & 3];

    const ulonglong2* Wp0 = (const ulonglong2*)&Wsm[warp * KSL][0];
    unsigned* cnt = &g_count;

    for (int t = 1; t < Tq; ++t) {
        const float4* Sp = ((const float4*)g_S4[(t - 1) & 1]) + warp * (ITS * Bq) + lane;

        float xin = epi ? outp[(size_t)t * Nq] : 0.f;  // barrier-independent; issue early

        // fill depth-8 pipeline of L2-only state loads
        float4 buf[8];
#pragma unroll
        for (int j = 0; j < 8; ++j) buf[j] = __ldcg(Sp + j * Bq);

        unsigned long long a0 = 0, a1 = 0, a2 = 0, a3 = 0;
        const ulonglong2* wp = Wp0;

#pragma unroll
        for (int it = 0; it < ITS; ++it) {
            float4 s = buf[it & 7];
            if (it < ITS - 8) buf[it & 7] = __ldcg(Sp + (it + 8) * Bq);
#pragma unroll
            for (int kk = 0; kk < 4; ++kk) {
                unsigned sb = __float_as_uint(kk == 0 ? s.x : kk == 1 ? s.y
                                                         : kk == 2 ? s.z : s.w);
                unsigned long long svv;
                asm("mov.b64 %0, {%1, %1};" : "=l"(svv) : "r"(sb));
                ulonglong2 u0 = wp[0];
                ulonglong2 u1 = wp[1];
                wp += 2;
                asm("fma.rn.f32x2 %0, %1, %2, %0;" : "+l"(a0) : "l"(svv), "l"(u0.x));
                asm("fma.rn.f32x2 %0, %1, %2, %0;" : "+l"(a1) : "l"(svv), "l"(u0.y));
                asm("fma.rn.f32x2 %0, %1, %2, %0;" : "+l"(a2) : "l"(svv), "l"(u1.x));
                asm("fma.rn.f32x2 %0, %1, %2, %0;" : "+l"(a3) : "l"(svv), "l"(u1.y));
            }
        }

        red[warp][lane][0] = __uint_as_float((unsigned)a0);
        red[warp][lane][1] = __uint_as_float((unsigned)(a0 >> 32));
        red[warp][lane][2] = __uint_as_float((unsigned)a1);
        red[warp][lane][3] = __uint_as_float((unsigned)(a1 >> 32));
        red[warp][lane][4] = __uint_as_float((unsigned)a2);
        red[warp][lane][5] = __uint_as_float((unsigned)(a2 >> 32));
        red[warp][lane][6] = __uint_as_float((unsigned)a3);
        red[warp][lane][7] = __uint_as_float((unsigned)(a3 >> 32));
        __syncthreads();

        if (epi) {
            float sum = 0.f;
#pragma unroll
            for (int w = 0; w < NW; ++w) sum += red[w][eb][ec];

            float post = tanhf(sum + xin) + nz;
            outp[(size_t)t * Nq] = post;        // only our own sector — safe
            *((t & 1) ? sW1 : sW0) = post;      // next-step state (read via __ldcg)
        }

        // ---- grid barrier: counter arrive (release) + single acquiring poller ----
        __syncthreads();  // all CTA state writes done; establishes HB to thread 0
        if (tid == 0) {
            asm volatile("red.release.gpu.add.u32 [%0], %1;"
                         :: "l"(cnt), "r"(1u) : "memory");
            const unsigned target = (unsigned)GRID_G * (unsigned)t;
            unsigned v;
            do {
                asm volatile("ld.acquire.gpu.u32 %0, [%1];"
                             : "=r"(v) : "l"(cnt) : "memory");
                if (v < target) __nanosleep(16);
            } while (v < target);
        }
        __syncthreads();  // broadcast barrier completion
    }
}

extern "C" void kernel_launch(void* const* d_in, const int* in_sizes, int n_in,
                              void* d_out, int out_size) {
    (void)in_sizes; (void)n_in; (void)out_size;
    const float* x       = (const float*)d_in[0];
    const float* w_input = (const float*)d_in[1];
    const float* w_res   = (const float*)d_in[2];
    const float* w_scale = (const float*)d_in[3];
    const float* states0 = (const float*)d_in[4];
    const float* step0   = (const float*)d_in[5];
    const float* rnoise  = (const float*)d_in[6];
    float* out = (float*)d_out;

    init_kernel<<<128, 256>>>(states0, step0, out);
    dim3 g(8, 128);
    xin_gemm<<<g, 256>>>(x, w_input, w_scale, out);
    recur_kernel<<<GRID_G, NTHR>>>(w_res, rnoise, out);
}